// round 17
// baseline (speedup 1.0000x reference)
#include <cuda_runtime.h>
#include <cstdint>

// ============================================================================
// Problem shapes (fixed by reference setup_inputs)
// ============================================================================
#define BATCH      4
#define NPTS       8192
#define L_DIFF     98304       // 4*8192*3
#define L_STYLE    2048        // 4*512
#define L_CONTENT  1048576     // 4*1024*256
#define L_ID       98304

// Symmetric chamfer, row-pair packed (same hot loop as the 86.0us best).
// Block tile: 1024 rows x 256 cols. grid = 1024 chamfer + 12 MSE = 1036
// = EXACTLY 7 blocks/SM * 148 SMs -> single wave, zero tail.
// Finalization is folded into the ticket-winning last block (no 2nd launch).
#define THREADS     128
#define RP          4                      // row-pairs per thread (8 rows)
#define XBLOCK      (THREADS * 2 * RP)     // 1024 rows per block
#define CH_I        (NPTS / XBLOCK)        // 8
#define JT          256                    // cols per block
#define CH_J        (NPTS / JT)            // 32
#define NPAIR       (JT / 2)               // 128 col-pairs
#define CH_BLOCKS   (CH_I * CH_J * BATCH)  // 1024
#define MSE_BLOCKS  12
#define ALL_BLOCKS  (CH_BLOCKS + MSE_BLOCKS)   // 1036 = 7*148

// ============================================================================
// Scratch (device globals; zero-initialized by CUDA).
// g_enc[i] = 0xFFFFFFFF - float_bits(min d2); d2 >= 0 so every encoded value
// > 0 ==> 0 is the atomicMax identity == static init == post-reset state.
// The last block resets all state each call -> deterministic replays.
// ============================================================================
__device__ unsigned int g_enc[2 * BATCH * NPTS];   // [dir][b][i]
__device__ double       g_acc[4];                   // diff, style, content, identity
__device__ unsigned int g_ctr;                      // last-block ticket (auto-wrap)

// ============================================================================
// Packed f32x2 helpers (Blackwell; only reachable via PTX)
// ============================================================================
static __device__ __forceinline__ unsigned long long pk2(float lo, float hi) {
    unsigned long long r;
    asm("mov.b64 %0, {%1, %2};" : "=l"(r) : "f"(lo), "f"(hi));
    return r;
}
static __device__ __forceinline__ void upk2(unsigned long long v, float& lo, float& hi) {
    asm("mov.b64 {%0, %1}, %2;" : "=f"(lo), "=f"(hi) : "l"(v));
}
static __device__ __forceinline__ unsigned long long fma2(unsigned long long a,
                                                          unsigned long long b,
                                                          unsigned long long c) {
    unsigned long long d;
    asm("fma.rn.f32x2 %0, %1, %2, %3;" : "=l"(d) : "l"(a), "l"(b), "l"(c));
    return d;
}
static __device__ __forceinline__ unsigned long long mul2(unsigned long long a,
                                                          unsigned long long b) {
    unsigned long long d;
    asm("mul.rn.f32x2 %0, %1, %2;" : "=l"(d) : "l"(a), "l"(b));
    return d;
}
static __device__ __forceinline__ unsigned long long add2(unsigned long long a,
                                                          unsigned long long b) {
    unsigned long long d;
    asm("add.rn.f32x2 %0, %1, %2;" : "=l"(d) : "l"(a), "l"(b));
    return d;
}

// ============================================================================
// Symmetric chamfer tile, row-pair packed, shallow butterfly
// (hot loop UNCHANGED from the 86.0us best).
// ============================================================================
static __device__ __forceinline__ void chamfer_tile(
    int bid, const float* __restrict__ xo, const float* __restrict__ xc,
    unsigned long long* s_y, unsigned long long* s_part) {

    const int b  = bid >> 8;           // batch (0..3)
    const int ic = (bid >> 5) & 7;     // i-chunk (0..7)
    const int jc = bid & 31;           // j-chunk (0..31)
    const float* X = xo + (size_t)b * NPTS * 3;
    const float* Y = xc + (size_t)b * NPTS * 3;
    unsigned int* enc_row = g_enc + (size_t)b * NPTS;            // dir0
    unsigned int* enc_col = g_enc + (size_t)(BATCH + b) * NPTS;  // dir1

    const int t    = threadIdx.x;
    const int lane = t & 31;
    const int wid  = t >> 5;
    const int row0 = ic * XBLOCK + t;

    unsigned long long npx[RP], npy[RP], npz[RP], rsqp[RP];
    float rminA[RP], rminB[RP];
#pragma unroll
    for (int rp = 0; rp < RP; rp++) {
        int iA = row0 + (2 * rp) * THREADS;
        int iB = row0 + (2 * rp + 1) * THREADS;
        float ax = X[3 * iA], ay = X[3 * iA + 1], az = X[3 * iA + 2];
        float bx = X[3 * iB], by = X[3 * iB + 1], bz = X[3 * iB + 2];
        npx[rp]  = pk2(-2.0f * ax, -2.0f * bx);
        npy[rp]  = pk2(-2.0f * ay, -2.0f * by);
        npz[rp]  = pk2(-2.0f * az, -2.0f * bz);
        rsqp[rp] = pk2(ax * ax + ay * ay + az * az,
                       bx * bx + by * by + bz * bz);
        rminA[rp] = 3.4e38f;
        rminB[rp] = 3.4e38f;
    }

    // y tile: per col j, 4 DUPLICATED u64: (x,x),(y,y),(z,z),(q,q)
    const int jbase = jc * JT;
    for (int j = t; j < JT; j += THREADS) {
        const float* yj = Y + 3 * (jbase + j);
        float yx = yj[0], yy = yj[1], yz = yj[2];
        s_y[4 * j]     = pk2(yx, yx);
        s_y[4 * j + 1] = pk2(yy, yy);
        s_y[4 * j + 2] = pk2(yz, yz);
        float q = yx * yx + yy * yy + yz * yz;
        s_y[4 * j + 3] = pk2(q, q);
    }
    __syncthreads();

#pragma unroll 4
    for (int cp = 0; cp < NPAIR; cp++) {
        float cmin0 = 3.4e38f, cmin1 = 3.4e38f;
        {
            ulonglong2 va = *(const ulonglong2*)(s_y + 8 * cp);      // x0d, y0d
            ulonglong2 vb = *(const ulonglong2*)(s_y + 8 * cp + 2);  // z0d, q0d
#pragma unroll
            for (int rp = 0; rp < RP; rp++) {
                unsigned long long s0 = mul2(npx[rp], va.x);
                s0 = fma2(npy[rp], va.y, s0);
                s0 = fma2(npz[rp], vb.x, s0);
                unsigned long long tr = add2(s0, vb.y);
                unsigned long long tc = add2(s0, rsqp[rp]);
                float lA, lB;
                upk2(tr, lA, lB);
                rminA[rp] = fminf(rminA[rp], lA);
                rminB[rp] = fminf(rminB[rp], lB);
                upk2(tc, lA, lB);
                cmin0 = fminf(cmin0, fminf(lA, lB));
            }
        }
        {
            ulonglong2 vc = *(const ulonglong2*)(s_y + 8 * cp + 4);  // x1d, y1d
            ulonglong2 vd = *(const ulonglong2*)(s_y + 8 * cp + 6);  // z1d, q1d
#pragma unroll
            for (int rp = 0; rp < RP; rp++) {
                unsigned long long s1 = mul2(npx[rp], vc.x);
                s1 = fma2(npy[rp], vc.y, s1);
                s1 = fma2(npz[rp], vd.x, s1);
                unsigned long long tr = add2(s1, vd.y);
                unsigned long long tc = add2(s1, rsqp[rp]);
                float lA, lB;
                upk2(tr, lA, lB);
                rminA[rp] = fminf(rminA[rp], lA);
                rminB[rp] = fminf(rminB[rp], lB);
                upk2(tc, lA, lB);
                cmin1 = fminf(cmin1, fminf(lA, lB));
            }
        }
        // shallow butterfly: 3 steps -> lanes 0-3 hold mod-4-class mins
#pragma unroll
        for (int off = 16; off > 2; off >>= 1) {
            cmin0 = fminf(cmin0, __shfl_xor_sync(0xFFFFFFFFu, cmin0, off));
            cmin1 = fminf(cmin1, __shfl_xor_sync(0xFFFFFFFFu, cmin1, off));
        }
        if (lane < 4) s_part[(wid * NPAIR + cp) * 4 + lane] = pk2(cmin0, cmin1);
    }

    // row epilogue
#pragma unroll
    for (int rp = 0; rp < RP; rp++) {
        float qA, qB;
        upk2(rsqp[rp], qA, qB);
        int iA = row0 + (2 * rp) * THREADS;
        int iB = row0 + (2 * rp + 1) * THREADS;
        float d2A = fmaxf(qA + rminA[rp], 0.0f);
        float d2B = fmaxf(qB + rminB[rp], 0.0f);
        atomicMax(enc_row + iA, 0xFFFFFFFFu - __float_as_uint(d2A));
        atomicMax(enc_row + iB, 0xFFFFFFFFu - __float_as_uint(d2B));
    }

    // col epilogue
    __syncthreads();
    for (int cp = t; cp < NPAIR; cp += THREADS) {
        float m0 = 3.4e38f, m1 = 3.4e38f;
#pragma unroll
        for (int w = 0; w < 4; w++) {
#pragma unroll
            for (int g = 0; g < 4; g++) {
                float a, bb;
                upk2(s_part[(w * NPAIR + cp) * 4 + g], a, bb);
                m0 = fminf(m0, a);
                m1 = fminf(m1, bb);
            }
        }
        float q0, du, q1;
        upk2(s_y[8 * cp + 3], q0, du);
        upk2(s_y[8 * cp + 7], q1, du);
        float d20 = fmaxf(q0 + m0, 0.0f);
        float d21 = fmaxf(q1 + m1, 0.0f);
        int j = jbase + 2 * cp;
        atomicMax(enc_col + j,     0xFFFFFFFFu - __float_as_uint(d20));
        atomicMax(enc_col + j + 1, 0xFFFFFFFFu - __float_as_uint(d21));
    }
}

// ============================================================================
// MSE part (12 blocks; overlapped under the ~65us chamfer wave).
// ============================================================================
static __device__ __forceinline__ float mse_part_v4(const float4* __restrict__ a,
                                                    const float4* __restrict__ b,
                                                    int n4, int gid, int stride) {
    float s = 0.f;
    for (int i = gid; i < n4; i += stride) {
        float4 va = a[i], vb = b[i];
        float d0 = va.x - vb.x, d1 = va.y - vb.y, d2 = va.z - vb.z, d3 = va.w - vb.w;
        s += d0 * d0 + d1 * d1 + d2 * d2 + d3 * d3;
    }
    return s;
}

static __device__ __forceinline__ void mse_blocks(
    int m, const float* pred, const float* targ, const float* ssim,
    const float* sreal, const float* corg, const float* cgen,
    const float* xorg, const float* xid, float* sm) {

    const int gid    = m * THREADS + threadIdx.x;
    const int stride = MSE_BLOCKS * THREADS;

    float s[4];
    s[0] = mse_part_v4((const float4*)pred, (const float4*)targ,  L_DIFF / 4,    gid, stride);
    s[1] = mse_part_v4((const float4*)ssim, (const float4*)sreal, L_STYLE / 4,   gid, stride);
    s[2] = mse_part_v4((const float4*)corg, (const float4*)cgen,  L_CONTENT / 4, gid, stride);
    s[3] = mse_part_v4((const float4*)xorg, (const float4*)xid,   L_ID / 4,      gid, stride);

    if (threadIdx.x < 4) sm[threadIdx.x] = 0.f;
    __syncthreads();
#pragma unroll
    for (int k = 0; k < 4; k++) {
#pragma unroll
        for (int off = 16; off > 0; off >>= 1)
            s[k] += __shfl_down_sync(0xFFFFFFFFu, s[k], off);
        if ((threadIdx.x & 31) == 0) atomicAdd(&sm[k], s[k]);
    }
    __syncthreads();
    if (threadIdx.x < 4) atomicAdd(&g_acc[threadIdx.x], (double)sm[threadIdx.x]);
}

// ============================================================================
// Fused kernel: blocks [0,1024) chamfer, [1024,1036) MSE; the LAST block to
// finish (ticket, after threadfence) sums sqrt(min d2), writes the 6 outputs,
// and resets all state for the next graph replay.
// ============================================================================
__global__ void __launch_bounds__(THREADS, 7)
fused_kernel(const float* __restrict__ xo,   const float* __restrict__ xc,
             const float* __restrict__ pred, const float* __restrict__ targ,
             const float* __restrict__ ssim, const float* __restrict__ sreal,
             const float* __restrict__ corg, const float* __restrict__ cgen,
             const float* __restrict__ xid,
             float* __restrict__ out, int out_size) {
    __shared__ __align__(16) unsigned long long s_y[4 * JT];            // 8 KB
    __shared__ __align__(16) unsigned long long s_part[4 * NPAIR * 4];  // 16 KB
    __shared__ float s_fin[THREADS / 32];
    __shared__ bool  s_last;

    const int bid = blockIdx.x;
    if (bid < CH_BLOCKS) {
        chamfer_tile(bid, xo, xc, s_y, s_part);
    } else {
        mse_blocks(bid - CH_BLOCKS, pred, targ, ssim, sreal, corg, cgen, xo, xid,
                   (float*)s_part);
    }

    // ---- last-block finalization ----
    __threadfence();
    if (threadIdx.x == 0) {
        unsigned tk = atomicInc(&g_ctr, gridDim.x - 1);  // wraps to 0
        s_last = (tk == gridDim.x - 1);
    }
    __syncthreads();
    if (!s_last) return;

    const int tid  = threadIdx.x;
    const int lane = tid & 31;
    const int wid  = tid >> 5;

    // sqrt-sum of all 65536 encoded mins + reset to 0 (atomicMax identity)
    float cham = 0.f;
    const int total = 2 * BATCH * NPTS;
    for (int i = tid; i < total; i += 4 * THREADS) {   // 4-way MLP
        unsigned u0 = g_enc[i];
        unsigned u1 = g_enc[i + THREADS];
        unsigned u2 = g_enc[i + 2 * THREADS];
        unsigned u3 = g_enc[i + 3 * THREADS];
        g_enc[i] = 0u; g_enc[i + THREADS] = 0u;
        g_enc[i + 2 * THREADS] = 0u; g_enc[i + 3 * THREADS] = 0u;
        cham += sqrtf(__uint_as_float(0xFFFFFFFFu - u0));
        cham += sqrtf(__uint_as_float(0xFFFFFFFFu - u1));
        cham += sqrtf(__uint_as_float(0xFFFFFFFFu - u2));
        cham += sqrtf(__uint_as_float(0xFFFFFFFFu - u3));
    }
#pragma unroll
    for (int off = 16; off > 0; off >>= 1)
        cham += __shfl_down_sync(0xFFFFFFFFu, cham, off);
    if (lane == 0) s_fin[wid] = cham;
    __syncthreads();

    if (tid == 0) {
        double chsum = 0.0;
#pragma unroll
        for (int w = 0; w < THREADS / 32; w++) chsum += (double)s_fin[w];
        double diff     = g_acc[0] / (double)L_DIFF;
        double stylemse = g_acc[1] / (double)L_STYLE;
        double content  = g_acc[2] / (double)L_CONTENT;
        double identity = g_acc[3] / (double)L_ID;
        double cycle    = chsum / (double)(BATCH * NPTS * 2);
        double style    = -stylemse;
        double tot = diff + 0.5 * style + 0.5 * content + cycle + 0.5 * identity;
        if (out_size > 0) out[0] = (float)diff;
        if (out_size > 1) out[1] = (float)style;
        if (out_size > 2) out[2] = (float)content;
        if (out_size > 3) out[3] = (float)cycle;
        if (out_size > 4) out[4] = (float)identity;
        if (out_size > 5) out[5] = (float)tot;
        for (int i = 6; i < out_size; i++) out[i] = 0.f;
        // clean accumulators for the next replay
        g_acc[0] = 0.0; g_acc[1] = 0.0; g_acc[2] = 0.0; g_acc[3] = 0.0;
    }
}

// ============================================================================
// Launch (graph-capturable, ONE kernel). Inputs:
// 0 pred_noise, 1 target_noise, 2 style_sim, 3 style_real,
// 4 content_original, 5 content_generated, 6 x_cycle, 7 x_original, 8 x_identity
// ============================================================================
extern "C" void kernel_launch(void* const* d_in, const int* in_sizes, int n_in,
                              void* d_out, int out_size) {
    (void)n_in; (void)in_sizes;
    const float* pred  = (const float*)d_in[0];
    const float* targ  = (const float*)d_in[1];
    const float* ssim  = (const float*)d_in[2];
    const float* sreal = (const float*)d_in[3];
    const float* corg  = (const float*)d_in[4];
    const float* cgen  = (const float*)d_in[5];
    const float* xcyc  = (const float*)d_in[6];
    const float* xorg  = (const float*)d_in[7];
    const float* xid   = (const float*)d_in[8];
    float* out = (float*)d_out;

    fused_kernel<<<ALL_BLOCKS, THREADS>>>(xorg, xcyc, pred, targ, ssim, sreal,
                                          corg, cgen, xid, out, out_size);
}